// round 11
// baseline (speedup 1.0000x reference)
#include <cuda_runtime.h>
#include <cuda_bf16.h>
#include <cstdint>

#define B_ 16
#define T_ 2048
#define D_ 64
#define MQ 128
#define NK 64
#define NTILES 32
#define NTH 256

// smem: Q hi/lo (16KB each) + two K/V tile buffers (32KB each) + rowsums
#define QHI 0
#define QLO 16384
#define BUF0 32768
#define BUF1 65536
#define KHIo 0
#define KLOo 8192
#define VHIo 16384
#define VLOo 24576
#define RSM 98304
#define RIM 98816
#define SMEM_BYTES 99328

__device__ __forceinline__ uint32_t su32(const void* p){
    uint32_t a; asm("{ .reg .u64 t; cvta.to.shared.u64 t,%1; cvt.u32.u64 %0,t; }":"=r"(a):"l"(p)); return a;
}

#define LDSM4(r, a) asm volatile("ldmatrix.sync.aligned.m8n8.x4.shared.b16 {%0,%1,%2,%3}, [%4];" \
    : "=r"((r)[0]),"=r"((r)[1]),"=r"((r)[2]),"=r"((r)[3]) : "r"(a))
#define LDSM4T(r, a) asm volatile("ldmatrix.sync.aligned.m8n8.x4.trans.shared.b16 {%0,%1,%2,%3}, [%4];" \
    : "=r"((r)[0]),"=r"((r)[1]),"=r"((r)[2]),"=r"((r)[3]) : "r"(a))
#define MMA(c, a, b0, b1) asm volatile( \
    "mma.sync.aligned.m16n8k16.row.col.f32.bf16.bf16.f32 " \
    "{%0,%1,%2,%3}, {%4,%5,%6,%7}, {%8,%9}, {%0,%1,%2,%3};" \
    : "+f"((c)[0]),"+f"((c)[1]),"+f"((c)[2]),"+f"((c)[3]) \
    : "r"((a)[0]),"r"((a)[1]),"r"((a)[2]),"r"((a)[3]), "r"(b0),"r"(b1))

__device__ __forceinline__ unsigned short bhi(float x){return __bfloat16_as_ushort(__float2bfloat16_rn(x));}
__device__ __forceinline__ float bhf(unsigned short u){return __bfloat162float(__ushort_as_bfloat16(u));}
__device__ __forceinline__ uint32_t pkh(float a, float b){
    return (uint32_t)bhi(a) | ((uint32_t)bhi(b) << 16);
}
__device__ __forceinline__ uint32_t pkl(float a, float b){
    return (uint32_t)bhi(a - bhf(bhi(a))) | ((uint32_t)bhi(b - bhf(bhi(b))) << 16);
}

// store float4 (row r, 8B chunk dc) as hi/lo bf16, XOR-swizzled (rows = 64 bf16 = 128B)
__device__ __forceinline__ void st_hl(char* hi, char* lo, int r, int dc, float4 x){
    unsigned short h0=bhi(x.x),h1=bhi(x.y),h2=bhi(x.z),h3=bhi(x.w);
    uint2 hv = make_uint2((uint32_t)h0|((uint32_t)h1<<16), (uint32_t)h2|((uint32_t)h3<<16));
    uint2 lv = make_uint2((uint32_t)bhi(x.x-bhf(h0))|((uint32_t)bhi(x.y-bhf(h1))<<16),
                          (uint32_t)bhi(x.z-bhf(h2))|((uint32_t)bhi(x.w-bhf(h3))<<16));
    uint32_t off = (uint32_t)(r*128 + ((dc*8) ^ ((r&7)<<4)));
    *(uint2*)(hi+off)=hv; *(uint2*)(lo+off)=lv;
}

__global__ __launch_bounds__(NTH,1)
void sdpa_k1(const float* __restrict__ qg, const float* __restrict__ kg,
             const float* __restrict__ vg, const float* __restrict__ bg,
             float* __restrict__ og, float* __restrict__ ag)
{
    extern __shared__ char sm[];
    const uint32_t sb = su32(sm);
    float* RSf = (float*)(sm + RSM);
    float* RIf = (float*)(sm + RIM);
    const int tid = threadIdx.x, lane = tid & 31, w = tid >> 5;
    const int b = blockIdx.y, qt = blockIdx.x;
    const size_t bq = (size_t)b * T_ + qt * MQ;
    const int rw = w * 16;
    const int ldr = tid >> 4, lddc = tid & 15;

    // ---- Q -> smem hi/lo ; K tile 0 -> BUF0 ----
    {
        const float4* src = (const float4*)(qg + bq * D_);
        #pragma unroll
        for (int i = 0; i < 8; i++){ int f = tid + NTH*i; st_hl(sm+QHI, sm+QLO, f>>4, f&15, src[f]); }
        const float4* ks = (const float4*)(kg + (size_t)b*T_*D_);
        #pragma unroll
        for (int i = 0; i < 4; i++){
            int f = tid + NTH*i;
            st_hl(sm+BUF0+KHIo, sm+BUF0+KLOo, ldr+16*i, lddc, ks[f]);
        }
    }
    __syncthreads();

    // ---- Q fragments (A, m16k16), all 4 k-chunks ----
    uint32_t qh[4][4], ql[4][4];
    {
        int row = rw + (lane & 15);
        int gh  = lane >> 4;
        #pragma unroll
        for (int kc = 0; kc < 4; kc++){
            int c16 = 2*kc + gh;
            uint32_t off = (uint32_t)(row*128 + ((c16 ^ (row&7))<<4));
            LDSM4(qh[kc], sb + QHI + off);
            LDSM4(ql[kc], sb + QLO + off);
        }
    }

    const int qr = lane >> 2;
    const int qc = (lane & 3) * 2;
    float rs0 = 0.f, rs1 = 0.f;

    // =================== PASS 1: rowsums only (K + bias, no stores) ===================
    for (int t = 0; t < NTILES; t++){
        const int key0 = t * NK;
        const uint32_t cur = sb + (t & 1 ? BUF1 : BUF0);
        char* nxt = sm + ((t & 1) ? BUF0 : BUF1);

        float2 bb0[8], bb1[8];
        {
            const float* p0 = bg + (bq + rw + qr) * (size_t)T_ + key0 + qc;
            const float* p1 = p0 + 8 * (size_t)T_;
            #pragma unroll
            for (int n = 0; n < 8; n++){ bb0[n] = __ldcs((const float2*)(p0 + 8*n)); bb1[n] = __ldcs((const float2*)(p1 + 8*n)); }
        }
        float4 kp[4];
        if (t + 1 < NTILES){
            const float4* ks = (const float4*)(kg + ((size_t)b*T_ + key0 + NK) * D_);
            #pragma unroll
            for (int i = 0; i < 4; i++){ kp[i] = ks[tid + NTH*i]; }
        }
        #pragma unroll
        for (int n = 0; n < 8; n++){
            uint32_t kh[8], klv[8];
            {
                int key = 8*n + (lane & 7);
                int g   = lane >> 3;
                uint32_t o1 = (uint32_t)(key*128 + ((g ^ (key&7))<<4));
                uint32_t o2 = (uint32_t)(key*128 + (((g+4) ^ (key&7))<<4));
                LDSM4(kh+0,  cur + KHIo + o1);  LDSM4(kh+4,  cur + KHIo + o2);
                LDSM4(klv+0, cur + KLOo + o1);  LDSM4(klv+4, cur + KLOo + o2);
            }
            float s[4] = {0.f,0.f,0.f,0.f};
            #pragma unroll
            for (int kc = 0; kc < 4; kc++){
                MMA(s, qh[kc], kh[2*kc],  kh[2*kc+1]);
                MMA(s, qh[kc], klv[2*kc], klv[2*kc+1]);
                MMA(s, ql[kc], kh[2*kc],  kh[2*kc+1]);
            }
            rs0 += __expf(s[0]*0.125f + bb0[n].x) + __expf(s[1]*0.125f + bb0[n].y);
            rs1 += __expf(s[2]*0.125f + bb1[n].x) + __expf(s[3]*0.125f + bb1[n].y);
        }
        if (t + 1 < NTILES){
            #pragma unroll
            for (int i = 0; i < 4; i++) st_hl(nxt+KHIo, nxt+KLOo, ldr+16*i, lddc, kp[i]);
        }
        __syncthreads();
    }

    // ---- rowsum -> inverse ----
    rs0 += __shfl_xor_sync(0xffffffffu, rs0, 1); rs0 += __shfl_xor_sync(0xffffffffu, rs0, 2);
    rs1 += __shfl_xor_sync(0xffffffffu, rs1, 1); rs1 += __shfl_xor_sync(0xffffffffu, rs1, 2);
    if ((lane & 3) == 0){ RSf[rw + qr] = rs0; RSf[rw + qr + 8] = rs1; }
    __syncthreads();
    if (tid < MQ) RIf[tid] = __fdividef(1.f, RSf[tid]);
    __syncthreads();
    const float inv0 = RIf[rw + qr], inv1 = RIf[rw + qr + 8];

    // ---- reload K/V tile 0 into BUF0 ----
    {
        const float4* ks = (const float4*)(kg + (size_t)b*T_*D_);
        const float4* vs = (const float4*)(vg + (size_t)b*T_*D_);
        #pragma unroll
        for (int i = 0; i < 4; i++){
            int f = tid + NTH*i;
            st_hl(sm+BUF0+KHIo, sm+BUF0+KLOo, ldr+16*i, lddc, ks[f]);
            st_hl(sm+BUF0+VHIo, sm+BUF0+VLOo, ldr+16*i, lddc, vs[f]);
        }
    }
    float o[8][4];
    #pragma unroll
    for (int n = 0; n < 8; n++){ o[n][0]=0.f; o[n][1]=0.f; o[n][2]=0.f; o[n][3]=0.f; }
    __syncthreads();

    // =================== PASS 2: normalized attn + O ===================
    for (int t = 0; t < NTILES; t++){
        const int key0 = t * NK;
        const uint32_t cur = sb + (t & 1 ? BUF1 : BUF0);
        char* nxt = sm + ((t & 1) ? BUF0 : BUF1);

        float2 bb0[8], bb1[8];
        {
            const float* p0 = bg + (bq + rw + qr) * (size_t)T_ + key0 + qc;
            const float* p1 = p0 + 8 * (size_t)T_;
            #pragma unroll
            for (int n = 0; n < 8; n++){ bb0[n] = __ldcs((const float2*)(p0 + 8*n)); bb1[n] = __ldcs((const float2*)(p1 + 8*n)); }
        }
        float4 kp[4], vp[4];
        if (t + 1 < NTILES){
            const float4* ks = (const float4*)(kg + ((size_t)b*T_ + key0 + NK) * D_);
            const float4* vs = (const float4*)(vg + ((size_t)b*T_ + key0 + NK) * D_);
            #pragma unroll
            for (int i = 0; i < 4; i++){ int f = tid + NTH*i; kp[i] = ks[f]; vp[i] = vs[f]; }
        }

        uint32_t phi[4][4], plo[4][4];
        #pragma unroll
        for (int n = 0; n < 8; n++){
            uint32_t kh[8], klv[8];
            {
                int key = 8*n + (lane & 7);
                int g   = lane >> 3;
                uint32_t o1 = (uint32_t)(key*128 + ((g ^ (key&7))<<4));
                uint32_t o2 = (uint32_t)(key*128 + (((g+4) ^ (key&7))<<4));
                LDSM4(kh+0,  cur + KHIo + o1);  LDSM4(kh+4,  cur + KHIo + o2);
                LDSM4(klv+0, cur + KLOo + o1);  LDSM4(klv+4, cur + KLOo + o2);
            }
            float s[4] = {0.f,0.f,0.f,0.f};
            #pragma unroll
            for (int kc = 0; kc < 4; kc++){
                MMA(s, qh[kc], kh[2*kc],  kh[2*kc+1]);
                MMA(s, qh[kc], klv[2*kc], klv[2*kc+1]);
                MMA(s, ql[kc], kh[2*kc],  kh[2*kc+1]);
            }
            // normalized probabilities (bit-consistent with pass-1 p values)
            float p0 = __expf(s[0]*0.125f + bb0[n].x) * inv0;
            float p1 = __expf(s[1]*0.125f + bb0[n].y) * inv0;
            float p2 = __expf(s[2]*0.125f + bb1[n].x) * inv1;
            float p3 = __expf(s[3]*0.125f + bb1[n].y) * inv1;
            float* a0p = ag + (bq + rw + qr) * (size_t)T_ + key0 + 8*n + qc;
            __stcs((float2*)a0p, make_float2(p0, p1));
            __stcs((float2*)(a0p + 8*(size_t)T_), make_float2(p2, p3));
            int j = n >> 1, hfl = (n & 1) * 2;
            phi[j][hfl]   = pkh(p0, p1);  phi[j][hfl+1] = pkh(p2, p3);
            plo[j][hfl]   = pkl(p0, p1);  plo[j][hfl+1] = pkl(p2, p3);
        }
        #pragma unroll
        for (int n = 0; n < 8; n++){
            uint32_t vh[8], vl[8];
            {
                int key1 = lane, key2 = 32 + lane;
                uint32_t o1 = (uint32_t)(key1*128 + ((n ^ (key1&7))<<4));
                uint32_t o2 = (uint32_t)(key2*128 + ((n ^ (key2&7))<<4));
                LDSM4T(vh+0, cur + VHIo + o1);  LDSM4T(vh+4, cur + VHIo + o2);
                LDSM4T(vl+0, cur + VLOo + o1);  LDSM4T(vl+4, cur + VLOo + o2);
            }
            #pragma unroll
            for (int j = 0; j < 4; j++){
                MMA(o[n], phi[j], vh[2*j], vh[2*j+1]);
                MMA(o[n], phi[j], vl[2*j], vl[2*j+1]);
                MMA(o[n], plo[j], vh[2*j], vh[2*j+1]);
            }
        }
        if (t + 1 < NTILES){
            #pragma unroll
            for (int i = 0; i < 4; i++){
                st_hl(nxt+KHIo, nxt+KLOo, ldr+16*i, lddc, kp[i]);
                st_hl(nxt+VHIo, nxt+VLOo, ldr+16*i, lddc, vp[i]);
            }
        }
        __syncthreads();
    }

    // ---- O writeout (P was pre-normalized) ----
    {
        float* d0 = og + (bq + rw + qr) * (size_t)D_ + qc;
        float* d1 = og + (bq + rw + qr + 8) * (size_t)D_ + qc;
        #pragma unroll
        for (int n = 0; n < 8; n++){
            *(float2*)(d0 + 8*n) = make_float2(o[n][0], o[n][1]);
            *(float2*)(d1 + 8*n) = make_float2(o[n][2], o[n][3]);
        }
    }
}

extern "C" void kernel_launch(void* const* d_in, const int* in_sizes, int n_in,
                              void* d_out, int out_size) {
    const float* q    = (const float*)d_in[0];
    const float* k    = (const float*)d_in[1];
    const float* v    = (const float*)d_in[2];
    const float* bias = (const float*)d_in[3];
    float* out  = (float*)d_out;
    float* attn = out + (size_t)B_*T_*D_;

    cudaFuncSetAttribute(sdpa_k1, cudaFuncAttributeMaxDynamicSharedMemorySize, SMEM_BYTES);
    dim3 grid(T_/MQ, B_);
    sdpa_k1<<<grid, NTH, SMEM_BYTES>>>(q, k, v, bias, out, attn);
}

// round 13
// speedup vs baseline: 1.3445x; 1.3445x over previous
#include <cuda_runtime.h>
#include <cuda_bf16.h>
#include <cstdint>

#define B_ 16
#define T_ 2048
#define D_ 64
#define MQ 128
#define NK 64
#define NTILES 32
#define NTH 256

// smem byte offsets
#define QHI 0
#define QLO 16384
#define BUF0 32768              // each buf: khi 8K | klo 8K | vhi 8K | vlo 8K = 32KB
#define BUF1 65536
#define KHIo 0
#define KLOo 8192
#define VHIo 16384
#define VLOo 24576
#define BIA0 98304              // 128 rows x 272B = 34816
#define BIA1 133120
#define RSM  167936
#define RIM  168448
#define SMEM_BYTES 168960

__device__ float g_inv[B_ * T_];
__device__ unsigned short g_khi[2097152], g_klo[2097152];
__device__ unsigned short g_vhi[2097152], g_vlo[2097152];

__device__ __forceinline__ uint32_t su32(const void* p){
    uint32_t a; asm("{ .reg .u64 t; cvta.to.shared.u64 t,%1; cvt.u32.u64 %0,t; }":"=r"(a):"l"(p)); return a;
}
#define CPA(dst, src) asm volatile("cp.async.cg.shared.global [%0], [%1], 16;" :: "r"(dst), "l"(src) : "memory")
#define CPCOMMIT()    asm volatile("cp.async.commit_group;" ::: "memory")
#define CPWAIT0()     asm volatile("cp.async.wait_group 0;" ::: "memory")

#define LDSM4(r, a) asm volatile("ldmatrix.sync.aligned.m8n8.x4.shared.b16 {%0,%1,%2,%3}, [%4];" \
    : "=r"((r)[0]),"=r"((r)[1]),"=r"((r)[2]),"=r"((r)[3]) : "r"(a))
#define LDSM4T(r, a) asm volatile("ldmatrix.sync.aligned.m8n8.x4.trans.shared.b16 {%0,%1,%2,%3}, [%4];" \
    : "=r"((r)[0]),"=r"((r)[1]),"=r"((r)[2]),"=r"((r)[3]) : "r"(a))
#define MMA(c, a, b0, b1) asm volatile( \
    "mma.sync.aligned.m16n8k16.row.col.f32.bf16.bf16.f32 " \
    "{%0,%1,%2,%3}, {%4,%5,%6,%7}, {%8,%9}, {%0,%1,%2,%3};" \
    : "+f"((c)[0]),"+f"((c)[1]),"+f"((c)[2]),"+f"((c)[3]) \
    : "r"((a)[0]),"r"((a)[1]),"r"((a)[2]),"r"((a)[3]), "r"(b0),"r"(b1))

__device__ __forceinline__ unsigned short bhi(float x){return __bfloat16_as_ushort(__float2bfloat16_rn(x));}
__device__ __forceinline__ float bhf(unsigned short u){return __bfloat162float(__ushort_as_bfloat16(u));}
__device__ __forceinline__ uint32_t pkh(float a, float b){
    return (uint32_t)bhi(a) | ((uint32_t)bhi(b) << 16);
}
__device__ __forceinline__ uint32_t pkl(float a, float b){
    return (uint32_t)bhi(a - bhf(bhi(a))) | ((uint32_t)bhi(b - bhf(bhi(b))) << 16);
}
__device__ __forceinline__ void st_hl(char* hi, char* lo, int r, int dc, float4 x){
    unsigned short h0=bhi(x.x),h1=bhi(x.y),h2=bhi(x.z),h3=bhi(x.w);
    uint2 hv = make_uint2((uint32_t)h0|((uint32_t)h1<<16), (uint32_t)h2|((uint32_t)h3<<16));
    uint2 lv = make_uint2((uint32_t)bhi(x.x-bhf(h0))|((uint32_t)bhi(x.y-bhf(h1))<<16),
                          (uint32_t)bhi(x.z-bhf(h2))|((uint32_t)bhi(x.w-bhf(h3))<<16));
    uint32_t off = (uint32_t)(r*128 + ((dc*8) ^ ((r&7)<<4)));
    *(uint2*)(hi+off)=hv; *(uint2*)(lo+off)=lv;
}

// ---- k0: convert K,V fp32 -> bf16 hi/lo scratch (row-major [b][t][d]) ----
__global__ __launch_bounds__(256) void cvt_kv(const float* __restrict__ kg, const float* __restrict__ vg){
    int i = blockIdx.x * blockDim.x + threadIdx.x;      // 0..1048575 (float4 groups)
    const float* src; unsigned short *hi, *lo; int e;
    if (i < 524288){ src = kg; hi = g_khi; lo = g_klo; e = i; }
    else           { src = vg; hi = g_vhi; lo = g_vlo; e = i - 524288; }
    float4 x = ((const float4*)src)[e];
    unsigned short h0=bhi(x.x),h1=bhi(x.y),h2=bhi(x.z),h3=bhi(x.w);
    ((uint2*)hi)[e] = make_uint2((uint32_t)h0|((uint32_t)h1<<16), (uint32_t)h2|((uint32_t)h3<<16));
    ((uint2*)lo)[e] = make_uint2((uint32_t)bhi(x.x-bhf(h0))|((uint32_t)bhi(x.y-bhf(h1))<<16),
                                 (uint32_t)bhi(x.z-bhf(h2))|((uint32_t)bhi(x.w-bhf(h3))<<16));
}

__global__ __launch_bounds__(NTH,1)
void sdpa_k1(const float* __restrict__ qg, const float* __restrict__ bg,
             float* __restrict__ og, float* __restrict__ ag)
{
    extern __shared__ char sm[];
    const uint32_t sb = su32(sm);
    float* RSf = (float*)(sm + RSM);
    float* RIf = (float*)(sm + RIM);
    const int tid = threadIdx.x, lane = tid & 31, w = tid >> 5;
    const int b = blockIdx.y, qt = blockIdx.x;
    const size_t bq = (size_t)b * T_ + qt * MQ;
    const int rw = w * 16;

    // ---- async tile issue: K/V bf16 hi/lo (swizzled) + bias (row stride 272B) ----
    auto issue_tile = [&](int t){
        const uint32_t bufb = sb + ((t & 1) ? BUF1 : BUF0);
        const uint32_t biab = sb + ((t & 1) ? BIA1 : BIA0);
        const size_t boff = (size_t)b * T_ + t * NK;
        const unsigned short* srcs[4] = {g_khi, g_klo, g_vhi, g_vlo};
        #pragma unroll
        for (int a = 0; a < 4; a++){
            #pragma unroll
            for (int j = 0; j < 2; j++){
                int ch = tid + 256*j;               // 512 chunks (64 rows x 8)
                int r = ch >> 3, c = ch & 7;
                uint32_t dst = bufb + a*8192 + r*128 + ((c ^ (r&7)) << 4);
                CPA(dst, srcs[a] + (boff + r)*64 + c*8);
            }
        }
        #pragma unroll
        for (int j = 0; j < 8; j++){
            int ch = tid + 256*j;                   // 2048 chunks (128 rows x 16)
            int r = ch >> 4, c = ch & 15;
            CPA(biab + r*272 + c*16, bg + (bq + r)*(size_t)T_ + t*NK + c*4);
        }
        CPCOMMIT();
    };

    // ---- Q -> smem hi/lo; start tile 0 async ----
    {
        const float4* src = (const float4*)(qg + bq * D_);
        #pragma unroll
        for (int i = 0; i < 8; i++){ int f = tid + NTH*i; st_hl(sm+QHI, sm+QLO, f>>4, f&15, src[f]); }
    }
    issue_tile(0);
    CPWAIT0();
    __syncthreads();

    // ---- Q fragments ----
    uint32_t qh[4][4], ql[4][4];
    {
        int row = rw + (lane & 15);
        int gh  = lane >> 4;
        #pragma unroll
        for (int kc = 0; kc < 4; kc++){
            int c16 = 2*kc + gh;
            uint32_t off = (uint32_t)(row*128 + ((c16 ^ (row&7))<<4));
            LDSM4(qh[kc], sb + QHI + off);
            LDSM4(ql[kc], sb + QLO + off);
        }
    }

    float o[8][4];
    #pragma unroll
    for (int n = 0; n < 8; n++){ o[n][0]=0.f; o[n][1]=0.f; o[n][2]=0.f; o[n][3]=0.f; }
    float rs0 = 0.f, rs1 = 0.f;
    const int qr = lane >> 2;
    const int qc = (lane & 3) * 2;

    for (int t = 0; t < NTILES; t++){
        const int key0 = t * NK;
        const uint32_t cur = sb + ((t & 1) ? BUF1 : BUF0);
        const char* biac = sm + ((t & 1) ? BIA1 : BIA0);

        if (t + 1 < NTILES) issue_tile(t + 1);

        // ---- S = Q.K^T, exp, attn store, pack P ----
        uint32_t phi[4][4], plo[4][4];
        #pragma unroll
        for (int n = 0; n < 8; n++){
            uint32_t kh[8], klv[8];
            {
                int key = 8*n + (lane & 7);
                int g   = lane >> 3;
                uint32_t o1 = (uint32_t)(key*128 + ((g ^ (key&7))<<4));
                uint32_t o2 = (uint32_t)(key*128 + (((g+4) ^ (key&7))<<4));
                LDSM4(kh+0,  cur + KHIo + o1);  LDSM4(kh+4,  cur + KHIo + o2);
                LDSM4(klv+0, cur + KLOo + o1);  LDSM4(klv+4, cur + KLOo + o2);
            }
            float s[4] = {0.f,0.f,0.f,0.f};
            #pragma unroll
            for (int kc = 0; kc < 4; kc++){
                MMA(s, qh[kc], kh[2*kc],  kh[2*kc+1]);
                MMA(s, qh[kc], klv[2*kc], klv[2*kc+1]);
                MMA(s, ql[kc], kh[2*kc],  kh[2*kc+1]);
            }
            float2 bb0 = *(const float2*)(biac + (rw + qr)*272 + (8*n + qc)*4);
            float2 bb1 = *(const float2*)(biac + (rw + qr + 8)*272 + (8*n + qc)*4);
            float p0 = __expf(s[0]*0.125f + bb0.x);
            float p1 = __expf(s[1]*0.125f + bb0.y);
            float p2 = __expf(s[2]*0.125f + bb1.x);
            float p3 = __expf(s[3]*0.125f + bb1.y);
            rs0 += p0 + p1;  rs1 += p2 + p3;
            float* a0p = ag + (bq + rw + qr) * (size_t)T_ + key0 + 8*n + qc;
            __stcs((float2*)a0p, make_float2(p0, p1));
            __stcs((float2*)(a0p + 8*(size_t)T_), make_float2(p2, p3));
            int j = n >> 1, hfl = (n & 1) * 2;
            phi[j][hfl]   = pkh(p0, p1);  phi[j][hfl+1] = pkh(p2, p3);
            plo[j][hfl]   = pkl(p0, p1);  plo[j][hfl+1] = pkl(p2, p3);
        }
        // ---- O += P.V ----
        #pragma unroll
        for (int n = 0; n < 8; n++){
            uint32_t vh[8], vl[8];
            {
                int key1 = lane, key2 = 32 + lane;
                uint32_t o1 = (uint32_t)(key1*128 + ((n ^ (key1&7))<<4));
                uint32_t o2 = (uint32_t)(key2*128 + ((n ^ (key2&7))<<4));
                LDSM4T(vh+0, cur + VHIo + o1);  LDSM4T(vh+4, cur + VHIo + o2);
                LDSM4T(vl+0, cur + VLOo + o1);  LDSM4T(vl+4, cur + VLOo + o2);
            }
            #pragma unroll
            for (int j = 0; j < 4; j++){
                MMA(o[n], phi[j], vh[2*j], vh[2*j+1]);
                MMA(o[n], phi[j], vl[2*j], vl[2*j+1]);
                MMA(o[n], plo[j], vh[2*j], vh[2*j+1]);
            }
        }
        if (t + 1 < NTILES) CPWAIT0();
        __syncthreads();
    }

    // ---- rowsums ----
    rs0 += __shfl_xor_sync(0xffffffffu, rs0, 1); rs0 += __shfl_xor_sync(0xffffffffu, rs0, 2);
    rs1 += __shfl_xor_sync(0xffffffffu, rs1, 1); rs1 += __shfl_xor_sync(0xffffffffu, rs1, 2);
    if ((lane & 3) == 0){ RSf[rw + qr] = rs0; RSf[rw + qr + 8] = rs1; }
    __syncthreads();
    if (tid < MQ){ float inv = __fdividef(1.f, RSf[tid]); RIf[tid] = inv; g_inv[bq + tid] = inv; }
    __syncthreads();

    // ---- O writeout (normalized) ----
    {
        float inv0 = RIf[rw + qr], inv1 = RIf[rw + qr + 8];
        float* d0 = og + (bq + rw + qr) * (size_t)D_ + qc;
        float* d1 = og + (bq + rw + qr + 8) * (size_t)D_ + qc;
        #pragma unroll
        for (int n = 0; n < 8; n++){
            *(float2*)(d0 + 8*n) = make_float2(o[n][0]*inv0, o[n][1]*inv0);
            *(float2*)(d1 + 8*n) = make_float2(o[n][2]*inv1, o[n][3]*inv1);
        }
    }
}

__global__ void sdpa_k2(float* __restrict__ ag){
    const size_t nf4 = (size_t)B_*T_*T_/4;
    size_t i = (size_t)blockIdx.x*blockDim.x + threadIdx.x;
    size_t stride = (size_t)gridDim.x*blockDim.x;
    for (size_t f = i; f < nf4; f += stride){
        float inv = g_inv[f >> 9];
        float4* p = (float4*)ag + f;
        float4 v = __ldcs(p);
        v.x*=inv; v.y*=inv; v.z*=inv; v.w*=inv;
        __stcs(p, v);
    }
}

extern "C" void kernel_launch(void* const* d_in, const int* in_sizes, int n_in,
                              void* d_out, int out_size) {
    const float* q    = (const float*)d_in[0];
    const float* k    = (const float*)d_in[1];
    const float* v    = (const float*)d_in[2];
    const float* bias = (const float*)d_in[3];
    float* out  = (float*)d_out;
    float* attn = out + (size_t)B_*T_*D_;

    cvt_kv<<<4096, 256>>>(k, v);
    cudaFuncSetAttribute(sdpa_k1, cudaFuncAttributeMaxDynamicSharedMemorySize, SMEM_BYTES);
    dim3 grid(T_/MQ, B_);
    sdpa_k1<<<grid, NTH, SMEM_BYTES>>>(q, bias, out, attn);
    sdpa_k2<<<8192, 256>>>(attn);
}